// round 5
// baseline (speedup 1.0000x reference)
#include <cuda_runtime.h>
#include <cuda_bf16.h>

// ArcSoftmaxLoss: loss = mean_b [ logsumexp_j(64*costh) - target_b ]
// with the label column replaced by 64*cos(acos(c_y)+margin).
//
// Fixed-max LSE (M = 63.36 >= all logits since |costh|<0.99); streaming row
// sum with NO label check; label column fixed up once per row by thread 0.
//
// exp via packed f32x2 (Blackwell) 2^(x/2) polynomial, then squared:
//  - f32x2 fma/add/mul halve FMA-pipe instruction count vs scalar
//  - half-exponent + square removes the underflow clamp (x/2 >= -91.4 keeps
//    the exponent-bit reconstruction from wrapping; square underflows to ~0)
//  - m<<23 == bits(r)<<23 because the magic constant's low 9 bits are zero
//
// Single compute kernel: memset node zeroes out[0]; each block atomicAdds its
// row loss / BATCH. Label gather prefetched at kernel entry to hide latency.

#define BATCH 512
#define NCLS  100000
#define NVEC  (NCLS / 4)
#define THREADS 512

#define LOG2E 1.4426950408889634f
#define MMAX  63.36f
#define K1    (64.0f * LOG2E)
#define K2    (-MMAX * LOG2E)
#define K1H   (0.5f * K1)            // half-exponent variant
#define K2H   (0.5f * K2)
#define COS_M 0.8775825618903728f    // cos(0.5)
#define SIN_M 0.47942553860420300f   // sin(0.5)

typedef unsigned long long ull;

__device__ __forceinline__ ull f2fma(ull a, ull b, ull c) {
    ull d; asm("fma.rn.f32x2 %0, %1, %2, %3;" : "=l"(d) : "l"(a), "l"(b), "l"(c)); return d;
}
__device__ __forceinline__ ull f2add(ull a, ull b) {
    ull d; asm("add.rn.f32x2 %0, %1, %2;" : "=l"(d) : "l"(a), "l"(b)); return d;
}
__device__ __forceinline__ ull f2mul(ull a, ull b) {
    ull d; asm("mul.rn.f32x2 %0, %1, %2;" : "=l"(d) : "l"(a), "l"(b)); return d;
}
__device__ __forceinline__ ull pk2(float f) {
    unsigned u = __float_as_uint(f); return (ull)u | ((ull)u << 32);
}

// Packed: exp(64*c - MMAX) for both lanes of c, via (2^((64c-MMAX)*log2e/2))^2.
__device__ __forceinline__ ull exp_shift_x2(ull c) {
    const ull k1h   = pk2(K1H);
    const ull k2h   = pk2(K2H);
    const ull magic = pk2(12582912.0f);      // 1.5 * 2^23
    const ull nmag  = pk2(-12582912.0f);
    const ull none  = pk2(-1.0f);
    const ull c5 = pk2(1.33336e-3f);
    const ull c4 = pk2(9.61813e-3f);
    const ull c3 = pk2(5.550411e-2f);
    const ull c2 = pk2(2.4022651e-1f);
    const ull c1 = pk2(6.9314718e-1f);
    const ull c0 = pk2(1.0f);

    ull y  = f2fma(c, k1h, k2h);             // (64c - M)*log2e/2, in [-91.4, 0]
    ull r  = f2add(y, magic);                // round-to-int in low bits
    ull nf = f2add(r, nmag);                 // integer part as float
    ull f  = f2fma(nf, none, y);             // frac in [-0.5, 0.5]
    ull p  = f2fma(c5, f, c4);
    p = f2fma(p, f, c3);
    p = f2fma(p, f, c2);
    p = f2fma(p, f, c1);
    p = f2fma(p, f, c0);
    // per-lane: e = bits(p) + (m << 23); m<<23 == bits(r)<<23 (magic low9 = 0)
    unsigned rlo = (unsigned)r, rhi = (unsigned)(r >> 32);
    unsigned plo = (unsigned)p, phi = (unsigned)(p >> 32);
    unsigned elo = plo + (rlo << 23);
    unsigned ehi = phi + (rhi << 23);
    ull e = (ull)elo | ((ull)ehi << 32);
    return f2mul(e, e);                      // square: full exponent, safe underflow
}

// Scalar version for the per-row fix-up (2 calls/row; clamp is fine here).
__device__ __forceinline__ float exp_shift_1(float c) {
    float x = fmaxf(fmaf(c, K1, K2), -125.0f);
    float r  = x + 12582912.0f;
    float nf = r - 12582912.0f;
    float f  = x - nf;
    int   m  = __float_as_int(r) - 0x4B400000;
    float p = 1.33336e-3f;
    p = fmaf(p, f, 9.61813e-3f);
    p = fmaf(p, f, 5.550411e-2f);
    p = fmaf(p, f, 2.4022651e-1f);
    p = fmaf(p, f, 6.9314718e-1f);
    p = fmaf(p, f, 1.0f);
    return __int_as_float(__float_as_int(p) + (m << 23));
}

__global__ __launch_bounds__(THREADS)
void arc_row_kernel(const float* __restrict__ costh,
                    const int* __restrict__ label,
                    float* __restrict__ out) {
    const int row = blockIdx.x;
    const float* rowp = costh + (size_t)row * NCLS;
    const float4* row4 = reinterpret_cast<const float4*>(rowp);

    // Prefetch the label gather early so its latency hides under the loop.
    int lab = 0;
    float cy = 0.f;
    if (threadIdx.x == 0) {
        lab = label[row];
        lab = max(0, min(lab, NCLS - 1));
        cy = __ldg(rowp + lab);
    }

    ull a0 = 0, a1 = 0;                      // packed accumulators (2 lanes each)
    #pragma unroll 4
    for (int v = threadIdx.x; v < NVEC; v += THREADS) {
        float4 c = __ldcs(row4 + v);         // streaming: no L2 reuse
        ull lo = (ull)__float_as_uint(c.x) | ((ull)__float_as_uint(c.y) << 32);
        ull hi = (ull)__float_as_uint(c.z) | ((ull)__float_as_uint(c.w) << 32);
        a0 = f2add(a0, exp_shift_x2(lo));
        a1 = f2add(a1, exp_shift_x2(hi));
    }
    ull a = f2add(a0, a1);
    float s = __uint_as_float((unsigned)a) + __uint_as_float((unsigned)(a >> 32));

    #pragma unroll
    for (int o = 16; o > 0; o >>= 1)
        s += __shfl_xor_sync(0xFFFFFFFFu, s, o);

    __shared__ float ws[THREADS / 32];
    const int wid = threadIdx.x >> 5;
    if ((threadIdx.x & 31) == 0) ws[wid] = s;
    __syncthreads();

    if (threadIdx.x == 0) {
        float tot = 0.f;
        #pragma unroll
        for (int i = 0; i < THREADS / 32; i++) tot += ws[i];

        // Replace target column's contribution.
        float sn = sqrtf(fmaxf(1.0f - cy * cy, 0.0f));
        const float cym = cy * COS_M - sn * SIN_M;   // cos(acos(cy)+0.5)
        const float target = 64.0f * cym;

        tot = tot - exp_shift_1(cy) + exp_shift_1(cym);

        const float loss = (MMAX + logf(tot)) - target;
        atomicAdd(out, loss * (1.0f / BATCH));
    }
}

extern "C" void kernel_launch(void* const* d_in, const int* in_sizes, int n_in,
                              void* d_out, int out_size) {
    const float* costh = (const float*)d_in[0];
    const int*   label = (const int*)d_in[1];
    float* out = (float*)d_out;

    cudaMemsetAsync(out, 0, sizeof(float));
    arc_row_kernel<<<BATCH, THREADS>>>(costh, label, out);
}

// round 7
// speedup vs baseline: 1.0706x; 1.0706x over previous
#include <cuda_runtime.h>
#include <cuda_bf16.h>

// ArcSoftmaxLoss: loss = mean_b [ logsumexp_j(64*costh) - target_b ],
// label column replaced by 64*cos(acos(c_y)+0.5).
//
// Fixed-max LSE (M = 63.36 >= all logits since |costh| < 0.99).
// Flat-range decomposition: 12.8M float4 split over 1184 blocks (148 SMs x 8,
// perfectly balanced, single wave at 256 thr / <=32 regs). Per-row partials
// accumulate via atomicAdd; a ticket counter elects the last block per row to
// do the label fix-up + log + mean contribution (no second kernel). Counters
// self-clean for graph replays.
//
// exp via clamp-free scalar 2^(x/2) poly squared into the accumulator:
//   acc = fmaf(eh, eh, acc);  eh >= 2^-92 so exponent reconstruction never
//   wraps, eh^2 underflows gracefully. 11 FMA/ALU ops per element.

#define BATCH  512
#define NCLS   100000
#define NVEC   (NCLS / 4)            // 25000 float4 per row
#define TOT4   (BATCH * NVEC)        // 12,800,000 float4 total
#define GRID   1184                  // 148 SMs * 8 blocks
#define NTHR   256
#define QCHUNK ((TOT4 + GRID - 1) / GRID)   // 10811 float4 per block

#define LOG2E 1.4426950408889634f
#define MMAX  63.36f                 // 64 * 0.99
#define K1H   (0.5f * 64.0f * LOG2E)
#define K2H   (0.5f * -MMAX * LOG2E)
#define COS_M 0.8775825618903728f    // cos(0.5)
#define SIN_M 0.47942553860420300f   // sin(0.5)

__device__ float    g_rowsum[BATCH];   // zero-init; finisher re-zeroes
__device__ unsigned g_count[BATCH];    // zero-init; finisher re-zeroes

// acc += exp(64*c - MMAX), via (2^((64c-M)*log2e/2))^2. No clamps.
__device__ __forceinline__ float expacc(float c, float acc) {
    float y = fmaf(c, K1H, K2H);                  // in [-91.4, 0]
    float r = y + 12582912.0f;                    // 1.5*2^23 round-to-int
    float f = y - (r - 12582912.0f);              // frac in [-0.5, 0.5]
    float p = fmaf(1.33336e-3f, f, 9.61813e-3f);  // 2^f Taylor
    p = fmaf(p, f, 5.550411e-2f);
    p = fmaf(p, f, 2.4022651e-1f);
    p = fmaf(p, f, 6.9314718e-1f);
    p = fmaf(p, f, 1.0f);
    // m<<23 == bits(r)<<23 (magic constant's low 9 bits are zero)
    float eh = __int_as_float(__float_as_int(p) + (__float_as_int(r) << 23));
    return fmaf(eh, eh, acc);
}

__device__ __forceinline__ float expv(float c) { return expacc(c, 0.0f); }

__global__ __launch_bounds__(NTHR, 8)
void arc_flat_kernel(const float* __restrict__ costh,
                     const int* __restrict__ label,
                     float* __restrict__ out) {
    const int tid = threadIdx.x;
    int s = blockIdx.x * QCHUNK;
    const int e = min(s + QCHUNK, TOT4);
    const float4* base4 = reinterpret_cast<const float4*>(costh);

    __shared__ float ws[NTHR / 32];

    while (s < e) {
        const int row     = s / NVEC;
        const int seg_end = min(e, (row + 1) * NVEC);

        // Prefetch the label gather so the (possible) finisher never stalls.
        float cy = 0.0f;
        if (tid == 0) {
            int lab = label[row];
            lab = max(0, min(lab, NCLS - 1));
            cy = __ldg(costh + (size_t)row * NCLS + lab);
        }

        // Streaming partial sum over [s, seg_end), coalesced.
        float s0 = 0.f, s1 = 0.f, s2 = 0.f, s3 = 0.f;
        #pragma unroll 4
        for (int v = s + tid; v < seg_end; v += NTHR) {
            float4 c = base4[v];
            s0 = expacc(c.x, s0);
            s1 = expacc(c.y, s1);
            s2 = expacc(c.z, s2);
            s3 = expacc(c.w, s3);
        }
        float part = (s0 + s1) + (s2 + s3);

        #pragma unroll
        for (int o = 16; o > 0; o >>= 1)
            part += __shfl_xor_sync(0xFFFFFFFFu, part, o);
        if ((tid & 31) == 0) ws[tid >> 5] = part;
        __syncthreads();

        if (tid == 0) {
            float blocksum = 0.f;
            #pragma unroll
            for (int i = 0; i < NTHR / 32; i++) blocksum += ws[i];

            atomicAdd(&g_rowsum[row], blocksum);
            __threadfence();                       // release rowsum before ticket
            unsigned old = atomicAdd(&g_count[row], 1u);

            // Number of blocks overlapping this row (contiguous Q-chunks).
            const int first = (row * NVEC) / QCHUNK;
            const int last  = ((row + 1) * NVEC - 1) / QCHUNK;
            const unsigned expected = (unsigned)(last - first + 1);

            if (old == expected - 1u) {            // last block for this row
                __threadfence();                   // acquire rowsum
                float tot = *((volatile float*)&g_rowsum[row]);

                // Replace the target column's contribution.
                float sn  = sqrtf(fmaxf(1.0f - cy * cy, 0.0f));
                float cym = cy * COS_M - sn * SIN_M;  // cos(acos(cy)+0.5)
                tot = tot - expv(cy) + expv(cym);

                float loss = (MMAX + logf(tot)) - 64.0f * cym;
                atomicAdd(out, loss * (1.0f / BATCH));

                // Self-clean for the next graph replay.
                g_count[row]  = 0u;
                *((volatile float*)&g_rowsum[row]) = 0.0f;
            }
        }
        __syncthreads();                           // ws reuse across segments
        s = seg_end;
    }
}

extern "C" void kernel_launch(void* const* d_in, const int* in_sizes, int n_in,
                              void* d_out, int out_size) {
    const float* costh = (const float*)d_in[0];
    const int*   label = (const int*)d_in[1];
    float* out = (float*)d_out;

    cudaMemsetAsync(out, 0, sizeof(float));
    arc_flat_kernel<<<GRID, NTHR>>>(costh, label, out);
}

// round 9
// speedup vs baseline: 1.1240x; 1.0499x over previous
#include <cuda_runtime.h>
#include <cuda_bf16.h>

// ArcSoftmaxLoss: loss = mean_b [ logsumexp_j(64*costh) - target_b ],
// label column replaced by 64*cos(acos(c_y)+0.5).
//
// Fixed-max LSE (M = 63.36 >= all logits since |costh| < 0.99).
// Flat-range decomposition: 12.8M float4 over 592 blocks (148 SMs x 4 CTAs,
// single balanced wave; oe=4 keeps the cross-CTA L1tex spread at its floor
// per the B300 spread law — oe=8 in R6 cost ~1.3x). Per-row partials via
// atomicAdd; ticket counter elects the last block per row to do the label
// fix-up + log + mean contribution. Counters self-clean for graph replays.
//
// exp via clamp-free 2^(x/2) degree-4 poly squared into the accumulator:
// 10 FMA/ALU ops per element, ~8e-5 rel err per term (tolerance 1e-3).

#define BATCH  512
#define NCLS   100000
#define NVEC   (NCLS / 4)            // 25000 float4 per row
#define TOT4   (BATCH * NVEC)        // 12,800,000 float4 total
#define GRID   592                   // 148 SMs * 4 CTAs
#define NTHR   256
#define QCHUNK ((TOT4 + GRID - 1) / GRID)   // 21622 float4 per block

#define LOG2E 1.4426950408889634f
#define MMAX  63.36f                 // 64 * 0.99
#define K1H   (0.5f * 64.0f * LOG2E)
#define K2H   (0.5f * -MMAX * LOG2E)
#define COS_M 0.8775825618903728f    // cos(0.5)
#define SIN_M 0.47942553860420300f   // sin(0.5)

__device__ float    g_rowsum[BATCH];   // zero-init; finisher re-zeroes
__device__ unsigned g_count[BATCH];    // zero-init; finisher re-zeroes

// acc += exp(64*c - MMAX), via (2^((64c-M)*log2e/2))^2. No clamps.
// Degree-4 2^f poly on [-0.5, 0.5]; half-exponent keeps the bit-trick safe
// (y/1 in [-91.4, 0], exponent never wraps), square underflows gracefully.
__device__ __forceinline__ float expacc(float c, float acc) {
    float y = fmaf(c, K1H, K2H);
    float r = y + 12582912.0f;                    // 1.5*2^23 round-to-int
    float f = y - (r - 12582912.0f);              // frac in [-0.5, 0.5]
    float p = fmaf(9.61844e-3f, f, 5.550411e-2f); // deg-4 2^f
    p = fmaf(p, f, 2.4022651e-1f);
    p = fmaf(p, f, 6.9314718e-1f);
    p = fmaf(p, f, 1.0f);
    // m<<23 == bits(r)<<23 (magic constant's low 9 bits are zero)
    float eh = __int_as_float(__float_as_int(p) + (__float_as_int(r) << 23));
    return fmaf(eh, eh, acc);
}

__device__ __forceinline__ float expv(float c) { return expacc(c, 0.0f); }

__global__ __launch_bounds__(NTHR)
void arc_flat_kernel(const float* __restrict__ costh,
                     const int* __restrict__ label,
                     float* __restrict__ out) {
    const int tid = threadIdx.x;
    int s = blockIdx.x * QCHUNK;
    const int e = min(s + QCHUNK, TOT4);
    const float4* base4 = reinterpret_cast<const float4*>(costh);

    __shared__ float ws[NTHR / 32];

    while (s < e) {
        const int row     = s / NVEC;
        const int seg_end = min(e, (row + 1) * NVEC);

        // Prefetch the label gather so the (possible) finisher never stalls.
        float cy = 0.0f;
        if (tid == 0) {
            int lab = label[row];
            lab = max(0, min(lab, NCLS - 1));
            cy = __ldg(costh + (size_t)row * NCLS + lab);
        }

        // Streaming partial sum over [s, seg_end), coalesced, 8-deep MLP.
        float s0 = 0.f, s1 = 0.f, s2 = 0.f, s3 = 0.f;
        #pragma unroll 8
        for (int v = s + tid; v < seg_end; v += NTHR) {
            float4 c = base4[v];
            s0 = expacc(c.x, s0);
            s1 = expacc(c.y, s1);
            s2 = expacc(c.z, s2);
            s3 = expacc(c.w, s3);
        }
        float part = (s0 + s1) + (s2 + s3);

        #pragma unroll
        for (int o = 16; o > 0; o >>= 1)
            part += __shfl_xor_sync(0xFFFFFFFFu, part, o);
        if ((tid & 31) == 0) ws[tid >> 5] = part;
        __syncthreads();

        if (tid == 0) {
            float blocksum = 0.f;
            #pragma unroll
            for (int i = 0; i < NTHR / 32; i++) blocksum += ws[i];

            atomicAdd(&g_rowsum[row], blocksum);
            __threadfence();                       // release rowsum before ticket
            unsigned old = atomicAdd(&g_count[row], 1u);

            // Number of blocks overlapping this row (contiguous Q-chunks).
            const int first = (row * NVEC) / QCHUNK;
            const int last  = ((row + 1) * NVEC - 1) / QCHUNK;
            const unsigned expected = (unsigned)(last - first + 1);

            if (old == expected - 1u) {            // last block for this row
                __threadfence();                   // acquire rowsum
                float tot = *((volatile float*)&g_rowsum[row]);

                // Replace the target column's contribution.
                float sn  = sqrtf(fmaxf(1.0f - cy * cy, 0.0f));
                float cym = cy * COS_M - sn * SIN_M;  // cos(acos(cy)+0.5)
                tot = tot - expv(cy) + expv(cym);

                float loss = (MMAX + logf(tot)) - 64.0f * cym;
                atomicAdd(out, loss * (1.0f / BATCH));

                // Self-clean for the next graph replay.
                g_count[row]  = 0u;
                *((volatile float*)&g_rowsum[row]) = 0.0f;
            }
        }
        __syncthreads();                           // ws reuse across segments
        s = seg_end;
    }
}

extern "C" void kernel_launch(void* const* d_in, const int* in_sizes, int n_in,
                              void* d_out, int out_size) {
    const float* costh = (const float*)d_in[0];
    const int*   label = (const int*)d_in[1];
    float* out = (float*)d_out;

    cudaMemsetAsync(out, 0, sizeof(float));
    arc_flat_kernel<<<GRID, NTHR>>>(costh, label, out);
}